// round 7
// baseline (speedup 1.0000x reference)
#include <cuda_runtime.h>

#define NODES  100000
#define F_IN   256
#define F_H    128
#define F_OUT  32
#define MAXE   1600000

// ---------------- scratch (no allocs allowed) ----------------
__device__ float g_h1  [(size_t)NODES * F_H];    // X @ W1
__device__ float g_agg1[(size_t)NODES * F_H];    // A_hat (X W1); relu(.)+b1 in place
__device__ float g_h2  [(size_t)NODES * F_OUT];  // relu @ W2
__device__ float g_agg2[(size_t)NODES * F_OUT];  // A_hat h2
__device__ float g_deg [NODES];
__device__ float g_dinv[NODES];
__device__ int   g_idx [(size_t)2 * MAXE];       // converted int32 edge indices
__device__ int   g_is64;                         // 1 if edge buffer is int64

// ---------------- dtype detection ----------------
// If the edge buffer is int64 (all values in [0, NODES) < 2^31), every odd
// 32-bit word is zero. For int32 data, 64 consecutive odd words all zero has
// probability ~0. One warp does the test.
__global__ void detect_kernel(const int* __restrict__ ei32, int n_words) {
    int tid = threadIdx.x;                 // 0..63
    int w = 0;
    int pos = 2 * tid + 1;
    if (pos < n_words) w = ei32[pos];
    // reduce across the 2 warps via shared
    __shared__ int any_nonzero;
    if (tid == 0) any_nonzero = 0;
    __syncthreads();
    if (w != 0) atomicOr(&any_nonzero, 1);
    __syncthreads();
    if (tid == 0) g_is64 = any_nonzero ? 0 : 1;
}

// ---------------- convert edges to int32 ----------------
__global__ void convert_kernel(const void* __restrict__ ei, int total) {
    int i = blockIdx.x * blockDim.x + threadIdx.x;
    if (i >= total) return;
    int v;
    if (g_is64) v = (int)((const long long*)ei)[i];
    else        v = ((const int*)ei)[i];
    g_idx[i] = v;
}

// ---------------- degree + normalization ----------------
__global__ void deg_kernel(const int* __restrict__ dst, int E) {
    int e = blockIdx.x * blockDim.x + threadIdx.x;
    if (e < E) atomicAdd(&g_deg[dst[e]], 1.0f);
}

__global__ void dinv_kernel(int n) {
    int i = blockIdx.x * blockDim.x + threadIdx.x;
    if (i < n) {
        float d = g_deg[i];
        g_dinv[i] = (d > 0.0f) ? rsqrtf(d) : 0.0f;
    }
}

// ---------------- register-tiled fp32 GEMM: C[MxN] = A[MxK] @ B[KxN] ----------------
template <int BM, int BN, int BK, int TM, int TN>
__global__ void gemm_kernel(const float* __restrict__ A, const float* __restrict__ B,
                            float* __restrict__ C, int M, int K, int N) {
    constexpr int NT = (BM / TM) * (BN / TN);
    __shared__ float As[BK][BM];      // transposed A tile
    __shared__ float Bs[BK][BN];

    const int tid  = threadIdx.x;
    const int tcol = tid % (BN / TN);
    const int trow = tid / (BN / TN);
    const int rowBase = blockIdx.x * BM;
    const int colBase = blockIdx.y * BN;

    float acc[TM][TN] = {};

    for (int k0 = 0; k0 < K; k0 += BK) {
        #pragma unroll 4
        for (int idx = tid; idx < BM * BK; idx += NT) {
            int r = idx / BK, c = idx % BK;
            int gr = rowBase + r;
            As[c][r] = (gr < M) ? A[(size_t)gr * K + k0 + c] : 0.0f;
        }
        #pragma unroll 4
        for (int idx = tid; idx < BK * BN; idx += NT) {
            int r = idx / BN, c = idx % BN;
            Bs[r][c] = B[(size_t)(k0 + r) * N + colBase + c];
        }
        __syncthreads();

        #pragma unroll
        for (int k = 0; k < BK; k++) {
            float rm[TM], rn[TN];
            #pragma unroll
            for (int i = 0; i < TM; i += 4) {
                float4 v = *reinterpret_cast<const float4*>(&As[k][trow * TM + i]);
                rm[i] = v.x; rm[i+1] = v.y; rm[i+2] = v.z; rm[i+3] = v.w;
            }
            {
                float4 v = *reinterpret_cast<const float4*>(&Bs[k][tcol * TN]);
                rn[0] = v.x; rn[1] = v.y; rn[2] = v.z; rn[3] = v.w;
            }
            #pragma unroll
            for (int i = 0; i < TM; i++)
                #pragma unroll
                for (int j = 0; j < TN; j++)
                    acc[i][j] += rm[i] * rn[j];
        }
        __syncthreads();
    }

    #pragma unroll
    for (int i = 0; i < TM; i++) {
        int gr = rowBase + trow * TM + i;
        if (gr < M) {
            float* cp = C + (size_t)gr * N + colBase + tcol * TN;
            float4 v = make_float4(acc[i][0], acc[i][1], acc[i][2], acc[i][3]);
            *reinterpret_cast<float4*>(cp) = v;
        }
    }
}

// ---------------- edge scatter: out[dst] += h[src] * dinv[src]*dinv[dst] ----------------
// One thread per (edge, 4-feature chunk). FV = F/4.
template <int FV>
__global__ void scatter_kernel(const float4* __restrict__ h,
                               const int* __restrict__ src,
                               const int* __restrict__ dst,
                               float* __restrict__ out, int E) {
    int t = blockIdx.x * blockDim.x + threadIdx.x;
    int total = E * FV;
    if (t >= total) return;
    int e = t / FV;
    int f = t % FV;
    int s = src[e];
    int d = dst[e];
    float norm = g_dinv[s] * g_dinv[d];
    float4 v = h[(size_t)s * FV + f];
    float* o = out + (size_t)d * (FV * 4) + f * 4;
    atomicAdd(o + 0, v.x * norm);
    atomicAdd(o + 1, v.y * norm);
    atomicAdd(o + 2, v.z * norm);
    atomicAdd(o + 3, v.w * norm);
}

// ---------------- bias + relu (in place, F_H = 128) ----------------
__global__ void relu_bias_kernel(float* __restrict__ a, const float* __restrict__ b, int total) {
    int i = blockIdx.x * blockDim.x + threadIdx.x;
    if (i < total) {
        float v = a[i] + b[i & (F_H - 1)];
        a[i] = v > 0.0f ? v : 0.0f;
    }
}

// ---------------- fused bias + log_softmax over 32 classes (one warp per node) ----------------
__global__ void logsoftmax_kernel(const float* __restrict__ agg, const float* __restrict__ b,
                                  float* __restrict__ out, int n) {
    int gt = blockIdx.x * blockDim.x + threadIdx.x;
    int node = gt >> 5;
    int lane = gt & 31;
    if (node >= n) return;
    float v = agg[(size_t)node * 32 + lane] + b[lane];
    float m = v;
    #pragma unroll
    for (int o = 16; o; o >>= 1) m = fmaxf(m, __shfl_xor_sync(0xffffffffu, m, o));
    float e = expf(v - m);
    float s = e;
    #pragma unroll
    for (int o = 16; o; o >>= 1) s += __shfl_xor_sync(0xffffffffu, s, o);
    out[(size_t)node * 32 + lane] = v - m - logf(s);
}

// ---------------- launch ----------------
extern "C" void kernel_launch(void* const* d_in, const int* in_sizes, int n_in,
                              void* d_out, int out_size) {
    const float* x   = (const float*)d_in[0];
    const float* W1  = (const float*)d_in[1];
    const float* b1  = (const float*)d_in[2];
    const float* W2  = (const float*)d_in[3];
    const float* b2  = (const float*)d_in[4];
    const void*  ei  = d_in[5];

    const int M = in_sizes[0] / F_IN;       // 100000
    const int E = in_sizes[5] / 2;          // 1600000

    float *h1, *agg1, *h2, *agg2, *deg;
    int *idx;
    cudaGetSymbolAddress((void**)&h1,   g_h1);
    cudaGetSymbolAddress((void**)&agg1, g_agg1);
    cudaGetSymbolAddress((void**)&h2,   g_h2);
    cudaGetSymbolAddress((void**)&agg2, g_agg2);
    cudaGetSymbolAddress((void**)&deg,  g_deg);
    cudaGetSymbolAddress((void**)&idx,  g_idx);

    const int* src = idx;
    const int* dst = idx + E;

    // zero accumulators
    cudaMemsetAsync(deg,  0, (size_t)M * sizeof(float));
    cudaMemsetAsync(agg1, 0, (size_t)M * F_H * sizeof(float));
    cudaMemsetAsync(agg2, 0, (size_t)M * F_OUT * sizeof(float));

    // edge dtype detect + convert to int32
    detect_kernel<<<1, 64>>>((const int*)ei, 2 * E);   // probe first 128 int32 words
    convert_kernel<<<(2 * E + 255) / 256, 256>>>(ei, 2 * E);

    // degree + D^{-1/2}
    deg_kernel<<<(E + 255) / 256, 256>>>(dst, E);
    dinv_kernel<<<(M + 255) / 256, 256>>>(M);

    // layer 1: h1 = x @ W1   (M x 256 @ 256 x 128)
    gemm_kernel<64, 128, 32, 8, 4>
        <<<dim3((M + 63) / 64, 1), 256>>>(x, W1, h1, M, F_IN, F_H);

    // aggregate layer 1
    {
        int total = E * (F_H / 4);
        scatter_kernel<F_H / 4><<<(total + 255) / 256, 256>>>(
            (const float4*)h1, src, dst, agg1, E);
    }

    // bias + relu in place
    relu_bias_kernel<<<((M * F_H) + 255) / 256, 256>>>(agg1, b1, M * F_H);

    // layer 2: h2 = relu_out @ W2   (M x 128 @ 128 x 32)
    gemm_kernel<128, 32, 32, 8, 4>
        <<<dim3((M + 127) / 128, 1), 128>>>(agg1, W2, h2, M, F_H, F_OUT);

    // aggregate layer 2
    {
        int total = E * (F_OUT / 4);
        scatter_kernel<F_OUT / 4><<<(total + 255) / 256, 256>>>(
            (const float4*)h2, src, dst, agg2, E);
    }

    // bias + log_softmax -> d_out
    logsoftmax_kernel<<<((M * 32) + 255) / 256, 256>>>(agg2, b2, (float*)d_out, M);
}

// round 10
// speedup vs baseline: 2.3739x; 2.3739x over previous
#include <cuda_runtime.h>

#define NODES  100000
#define F_IN   256
#define F_H    128
#define F_OUT  32
#define MAXE   1600000
#define SCANB  1024
#define NBLK   ((NODES + SCANB - 1) / SCANB)   // 98

// ---------------- scratch (no allocs allowed) ----------------
__device__ float g_h1 [(size_t)NODES * F_H];    // dinv-scaled X@W1
__device__ float g_rel[(size_t)NODES * F_H];    // layer-1 output (relu)
__device__ float g_h2 [(size_t)NODES * F_OUT];  // dinv-scaled relu@W2
__device__ int   g_src [MAXE];
__device__ int   g_dst [MAXE];
__device__ int   g_eidx[MAXE];                  // CSR column (src) indices
__device__ int   g_count [NODES];
__device__ int   g_rowptr[NODES + 1];
__device__ int   g_woff  [NODES];
__device__ int   g_bsum  [SCANB];
__device__ float g_dinv  [NODES];
__device__ int   g_is64;

// ---------------- edge dtype detection ----------------
// int64 indices < 2^31  =>  every odd 32-bit word is zero.
__global__ void detect_kernel(const int* __restrict__ ei32, int n_words) {
    int tid = threadIdx.x;                 // 0..63
    int w = 0;
    int pos = 2 * tid + 1;
    if (pos < n_words) w = ei32[pos];
    __shared__ int any_nonzero;
    if (tid == 0) any_nonzero = 0;
    __syncthreads();
    if (w != 0) atomicOr(&any_nonzero, 1);
    __syncthreads();
    if (tid == 0) g_is64 = any_nonzero ? 0 : 1;
}

// ---------------- convert to int32 + histogram of dst ----------------
__global__ void convert_hist_kernel(const void* __restrict__ ei, int E) {
    int e = blockIdx.x * blockDim.x + threadIdx.x;
    if (e >= E) return;
    int s, d;
    if (g_is64) {
        s = (int)((const long long*)ei)[e];
        d = (int)((const long long*)ei)[(size_t)E + e];
    } else {
        s = ((const int*)ei)[e];
        d = ((const int*)ei)[E + e];
    }
    g_src[e] = s;
    g_dst[e] = d;
    atomicAdd(&g_count[d], 1);
}

// ---------------- 3-kernel exclusive scan of g_count -> g_rowptr ----------------
__global__ void scan1_kernel(int n) {
    __shared__ int sh[SCANB];
    int tid = threadIdx.x;
    int i = blockIdx.x * SCANB + tid;
    int v = (i < n) ? g_count[i] : 0;
    sh[tid] = v;
    __syncthreads();
    #pragma unroll
    for (int o = 1; o < SCANB; o <<= 1) {
        int t = (tid >= o) ? sh[tid - o] : 0;
        __syncthreads();
        sh[tid] += t;
        __syncthreads();
    }
    if (i < n) g_rowptr[i + 1] = sh[tid];       // block-inclusive (offset added later)
    if (tid == SCANB - 1) g_bsum[blockIdx.x] = sh[tid];
}

__global__ void scan2_kernel(int nb) {          // one block, 128 threads, nb <= 128
    __shared__ int sh[128];
    int tid = threadIdx.x;
    int v = (tid < nb) ? g_bsum[tid] : 0;
    sh[tid] = v;
    __syncthreads();
    #pragma unroll
    for (int o = 1; o < 128; o <<= 1) {
        int t = (tid >= o) ? sh[tid - o] : 0;
        __syncthreads();
        sh[tid] += t;
        __syncthreads();
    }
    if (tid < nb) g_bsum[tid] = sh[tid] - v;    // exclusive block offsets
}

__global__ void scan3_kernel(int n) {
    int i = blockIdx.x * SCANB + threadIdx.x;
    if (i >= n) return;
    int off  = g_bsum[blockIdx.x];
    int incl = g_rowptr[i + 1] + off;           // global inclusive at i
    g_rowptr[i + 1] = incl;
    int cnt = g_count[i];
    g_woff[i] = incl - cnt;                     // row start (exclusive)
    g_dinv[i] = (cnt > 0) ? rsqrtf((float)cnt) : 0.0f;
    if (i == 0) g_rowptr[0] = 0;
}

// ---------------- CSR fill ----------------
__global__ void fill_kernel(int E) {
    int e = blockIdx.x * blockDim.x + threadIdx.x;
    if (e >= E) return;
    int d = g_dst[e];
    int pos = atomicAdd(&g_woff[d], 1);
    g_eidx[pos] = g_src[e];
}

// ---------------- register-tiled fp32 GEMM: C = (A @ B) * dinv[row] ----------------
// As padded (+1) to kill 32-way smem store conflicts; rm reads are scalar broadcasts.
template <int BM, int BN, int BK, int TM, int TN>
__global__ void gemm_kernel(const float* __restrict__ A, const float* __restrict__ B,
                            float* __restrict__ C, int M, int K, int N) {
    constexpr int NT = (BM / TM) * (BN / TN);
    __shared__ float As[BK][BM + 1];
    __shared__ float Bs[BK][BN];

    const int tid  = threadIdx.x;
    const int tcol = tid % (BN / TN);
    const int trow = tid / (BN / TN);
    const int rowBase = blockIdx.x * BM;
    const int colBase = blockIdx.y * BN;

    float acc[TM][TN] = {};

    for (int k0 = 0; k0 < K; k0 += BK) {
        #pragma unroll 4
        for (int idx = tid; idx < BM * BK; idx += NT) {
            int r = idx / BK, c = idx % BK;
            int gr = rowBase + r;
            As[c][r] = (gr < M) ? A[(size_t)gr * K + k0 + c] : 0.0f;
        }
        #pragma unroll 4
        for (int idx = tid; idx < BK * BN; idx += NT) {
            int r = idx / BN, c = idx % BN;
            Bs[r][c] = B[(size_t)(k0 + r) * N + colBase + c];
        }
        __syncthreads();

        #pragma unroll
        for (int k = 0; k < BK; k++) {
            float rm[TM], rn[TN];
            #pragma unroll
            for (int i = 0; i < TM; i++) rm[i] = As[k][trow * TM + i];
            {
                float4 v = *reinterpret_cast<const float4*>(&Bs[k][tcol * TN]);
                rn[0] = v.x; rn[1] = v.y; rn[2] = v.z; rn[3] = v.w;
            }
            #pragma unroll
            for (int i = 0; i < TM; i++)
                #pragma unroll
                for (int j = 0; j < TN; j++)
                    acc[i][j] += rm[i] * rn[j];
        }
        __syncthreads();
    }

    #pragma unroll
    for (int i = 0; i < TM; i++) {
        int gr = rowBase + trow * TM + i;
        if (gr < M) {
            float di = g_dinv[gr];
            float* cp = C + (size_t)gr * N + colBase + tcol * TN;
            float4 v = make_float4(acc[i][0] * di, acc[i][1] * di,
                                   acc[i][2] * di, acc[i][3] * di);
            *reinterpret_cast<float4*>(cp) = v;
        }
    }
}

// ---------------- layer-1 aggregation: warp per node, fused bias+relu ----------------
// g_rel[d] = relu( dinv[d] * sum_{src in row d} g_h1[src] + b1 )
__global__ void agg1_kernel(const float* __restrict__ b1, int n) {
    int warp = (blockIdx.x * blockDim.x + threadIdx.x) >> 5;
    int lane = threadIdx.x & 31;
    if (warp >= n) return;
    int beg = g_rowptr[warp], end = g_rowptr[warp + 1];
    const float4* h = (const float4*)g_h1;
    float4 acc = make_float4(0.f, 0.f, 0.f, 0.f);
    for (int j = beg; j < end; j += 32) {
        int e = (j + lane < end) ? g_eidx[j + lane] : 0;
        int cnt = min(32, end - j);
        for (int t = 0; t < cnt; t++) {
            int s = __shfl_sync(0xffffffffu, e, t);
            float4 v = h[(size_t)s * (F_H / 4) + lane];
            acc.x += v.x; acc.y += v.y; acc.z += v.z; acc.w += v.w;
        }
    }
    float di = g_dinv[warp];
    float4 b = ((const float4*)b1)[lane];
    float4 r;
    r.x = fmaxf(di * acc.x + b.x, 0.f);
    r.y = fmaxf(di * acc.y + b.y, 0.f);
    r.z = fmaxf(di * acc.z + b.z, 0.f);
    r.w = fmaxf(di * acc.w + b.w, 0.f);
    ((float4*)g_rel)[(size_t)warp * (F_H / 4) + lane] = r;
}

// ---------------- layer-2 aggregation fused with bias + log_softmax ----------------
// lane = class. out[d] = log_softmax( dinv[d] * sum g_h2[src] + b2 )
__global__ void agg2_softmax_kernel(const float* __restrict__ b2,
                                    float* __restrict__ out, int n) {
    int warp = (blockIdx.x * blockDim.x + threadIdx.x) >> 5;
    int lane = threadIdx.x & 31;
    if (warp >= n) return;
    int beg = g_rowptr[warp], end = g_rowptr[warp + 1];
    float acc = 0.f;
    for (int j = beg; j < end; j += 32) {
        int e = (j + lane < end) ? g_eidx[j + lane] : 0;
        int cnt = min(32, end - j);
        for (int t = 0; t < cnt; t++) {
            int s = __shfl_sync(0xffffffffu, e, t);
            acc += g_h2[(size_t)s * F_OUT + lane];
        }
    }
    float v = g_dinv[warp] * acc + b2[lane];
    float m = v;
    #pragma unroll
    for (int o = 16; o; o >>= 1) m = fmaxf(m, __shfl_xor_sync(0xffffffffu, m, o));
    float e = expf(v - m);
    float s = e;
    #pragma unroll
    for (int o = 16; o; o >>= 1) s += __shfl_xor_sync(0xffffffffu, s, o);
    out[(size_t)warp * F_OUT + lane] = v - m - logf(s);
}

// ---------------- launch ----------------
extern "C" void kernel_launch(void* const* d_in, const int* in_sizes, int n_in,
                              void* d_out, int out_size) {
    const float* x   = (const float*)d_in[0];
    const float* W1  = (const float*)d_in[1];
    const float* b1  = (const float*)d_in[2];
    const float* W2  = (const float*)d_in[3];
    const float* b2  = (const float*)d_in[4];
    const void*  ei  = d_in[5];

    const int M = in_sizes[0] / F_IN;       // 100000
    const int E = in_sizes[5] / 2;          // 1600000

    float *h1, *rel, *h2;
    int *cnt;
    cudaGetSymbolAddress((void**)&h1,  g_h1);
    cudaGetSymbolAddress((void**)&rel, g_rel);
    cudaGetSymbolAddress((void**)&h2,  g_h2);
    cudaGetSymbolAddress((void**)&cnt, g_count);

    // CSR build
    cudaMemsetAsync(cnt, 0, (size_t)M * sizeof(int));
    detect_kernel<<<1, 64>>>((const int*)ei, 2 * E);
    convert_hist_kernel<<<(E + 255) / 256, 256>>>(ei, E);
    scan1_kernel<<<NBLK, SCANB>>>(M);
    scan2_kernel<<<1, 128>>>(NBLK);
    scan3_kernel<<<NBLK, SCANB>>>(M);
    fill_kernel<<<(E + 255) / 256, 256>>>(E);

    // layer 1: h1 = dinv * (x @ W1)
    gemm_kernel<64, 128, 32, 8, 4>
        <<<dim3((M + 63) / 64, 1), 256>>>(x, W1, h1, M, F_IN, F_H);

    // aggregate + bias + relu
    agg1_kernel<<<(M * 32 + 255) / 256, 256>>>(b1, M);

    // layer 2: h2 = dinv * (rel @ W2)
    gemm_kernel<128, 32, 32, 8, 4>
        <<<dim3((M + 127) / 128, 1), 128>>>(rel, W2, h2, M, F_H, F_OUT);

    // aggregate + bias + log_softmax -> d_out
    agg2_softmax_kernel<<<(M * 32 + 255) / 256, 256>>>(b2, (float*)d_out, M);
}